// round 8
// baseline (speedup 1.0000x reference)
#include <cuda_runtime.h>
#include <math.h>
#include <stdint.h>

#define NUM_EXPERTS 64
#define D_MODEL     1024
#define N_TOKENS    4096
#define CAPACITY    512

// ---------------- scratch (static device globals; no runtime allocation) ----
__device__ int   d_count[NUM_EXPERTS];
__device__ int   d_tok[NUM_EXPERTS * CAPACITY];
__device__ int   d_slot[N_TOKENS * 2];
__device__ float d_wgt[N_TOKENS * 2];
__device__ float d_ybuf[(size_t)NUM_EXPERTS * CAPACITY * D_MODEL];   // 128 MiB

// ---------------- kernel 0 ---------------------------------------------------
__global__ void zero_counts_kernel() {
    if (threadIdx.x < NUM_EXPERTS) d_count[threadIdx.x] = 0;
}

// ---------------- kernel 1: gating GEMM + top-2 + routing --------------------
__global__ __launch_bounds__(256) void route_kernel(const float* __restrict__ x,
                                                    const float* __restrict__ gw) {
    __shared__ float Xs[32][64];
    __shared__ float Gs[32][64];
    __shared__ float Ls[64][65];

    const int t0  = blockIdx.x * 64;
    const int tid = threadIdx.x;
    const int tx  = tid & 15;
    const int ty  = tid >> 4;

    float acc[4][4];
#pragma unroll
    for (int i = 0; i < 4; i++)
#pragma unroll
        for (int j = 0; j < 4; j++) acc[i][j] = 0.f;

    for (int k0 = 0; k0 < D_MODEL; k0 += 32) {
#pragma unroll
        for (int i = 0; i < 2; i++) {
            int idx = tid + i * 256;
            int row = idx >> 3;
            int kq  = idx & 7;
            float4 v = *(const float4*)&x[(size_t)(t0 + row) * D_MODEL + k0 + kq * 4];
            Xs[kq * 4 + 0][row] = v.x;
            Xs[kq * 4 + 1][row] = v.y;
            Xs[kq * 4 + 2][row] = v.z;
            Xs[kq * 4 + 3][row] = v.w;
            float4 g = *(const float4*)&gw[(size_t)row * D_MODEL + k0 + kq * 4];
            Gs[kq * 4 + 0][row] = g.x;
            Gs[kq * 4 + 1][row] = g.y;
            Gs[kq * 4 + 2][row] = g.z;
            Gs[kq * 4 + 3][row] = g.w;
        }
        __syncthreads();
#pragma unroll
        for (int kk = 0; kk < 32; kk++) {
            float a[4], b[4];
            *(float4*)a = *(const float4*)&Xs[kk][ty * 4];
            *(float4*)b = *(const float4*)&Gs[kk][tx * 4];
#pragma unroll
            for (int i = 0; i < 4; i++)
#pragma unroll
                for (int j = 0; j < 4; j++) acc[i][j] += a[i] * b[j];
        }
        __syncthreads();
    }

#pragma unroll
    for (int i = 0; i < 4; i++)
#pragma unroll
        for (int j = 0; j < 4; j++) Ls[ty * 4 + i][tx * 4 + j] = acc[i][j];
    __syncthreads();

    if (tid < 64) {
        const int n = t0 + tid;
        float best = -INFINITY; int be = 0;
#pragma unroll
        for (int e = 0; e < NUM_EXPERTS; e++) {
            float v = Ls[tid][e];
            if (v > best) { best = v; be = e; }
        }
        float best2 = -INFINITY; int be2 = 0;
#pragma unroll
        for (int e = 0; e < NUM_EXPERTS; e++) {
            if (e == be) continue;
            float v = Ls[tid][e];
            if (v > best2) { best2 = v; be2 = e; }
        }
        float r  = expf(best2 - best);
        float w0 = 1.f / (1.f + r);
        float w1 = r / (1.f + r);

        int p0 = atomicAdd(&d_count[be],  1);
        int p1 = atomicAdd(&d_count[be2], 1);
        if (p0 < CAPACITY) {
            d_tok[be * CAPACITY + p0] = n;
            d_slot[n * 2 + 0] = be * CAPACITY + p0;
        } else d_slot[n * 2 + 0] = -1;
        if (p1 < CAPACITY) {
            d_tok[be2 * CAPACITY + p1] = n;
            d_slot[n * 2 + 1] = be2 * CAPACITY + p1;
        } else d_slot[n * 2 + 1] = -1;
        d_wgt[n * 2 + 0] = w0;
        d_wgt[n * 2 + 1] = w1;
    }
}

// ---------------- kernel 2: grouped GEMM, 3xTF32 tensor-core ------------------
// y[m,n] = sum_k x[tok[m],k] * W_e[n,k];  D = A(row) x B(col), B[k][n] = W[n][k].
#define TM 128
#define TN 128
#define TK 8
#define LDS_PAD 136   // 136 mod 32 == 8 -> fragment loads conflict-free

__device__ __forceinline__ uint32_t f2tf32(float f) {
    uint32_t u;
    asm("cvt.rna.tf32.f32 %0, %1;" : "=r"(u) : "f"(f));
    return u;
}

__device__ __forceinline__ void mma_tf32(float& d0, float& d1, float& d2, float& d3,
                                         uint32_t a0, uint32_t a1, uint32_t a2, uint32_t a3,
                                         uint32_t b0, uint32_t b1) {
    asm volatile(
        "mma.sync.aligned.m16n8k8.row.col.f32.tf32.tf32.f32 "
        "{%0,%1,%2,%3}, {%4,%5,%6,%7}, {%8,%9}, {%0,%1,%2,%3};"
        : "+f"(d0), "+f"(d1), "+f"(d2), "+f"(d3)
        : "r"(a0), "r"(a1), "r"(a2), "r"(a3), "r"(b0), "r"(b1));
}

__global__ __launch_bounds__(256, 2) void expert_gemm_kernel(const float* __restrict__ x,
                                                             const float* __restrict__ ew) {
    const int e = blockIdx.z;
    int cnt = d_count[e];
    if (cnt > CAPACITY) cnt = CAPACITY;
    const int m0 = blockIdx.y * TM;
    if (m0 >= cnt) return;
    const int n0 = blockIdx.x * TN;

    // hi/lo tf32 split tiles, k-major rows [k][m or n], double buffered.
    __shared__ float AsH[2][TK][LDS_PAD];
    __shared__ float AsL[2][TK][LDS_PAD];
    __shared__ float BsH[2][TK][LDS_PAD];
    __shared__ float BsL[2][TK][LDS_PAD];
    __shared__ int   toks[TM];

    const int tid = threadIdx.x;
    if (tid < TM) {
        int gr = m0 + tid;
        toks[tid] = (gr < cnt) ? d_tok[e * CAPACITY + gr] : 0;
    }
    __syncthreads();

    const float* __restrict__ W = ew + (size_t)e * D_MODEL * D_MODEL;

    // loader mapping: 256 float4 slots per matrix per k-tile (128 rows x 2 quads)
    const int lrow = tid >> 1;          // 0..127
    const int lkq  = tid & 1;           // 0..1  (float4 within 8 k)

    // mma mapping
    const int lane = tid & 31;
    const int grp  = lane >> 2;         // 0..7
    const int tc   = lane & 3;          // 0..3
    const int wid  = tid >> 5;          // 0..7
    const int wm   = wid & 3;           // 4 warps along M (32 rows each)
    const int wn   = wid >> 2;          // 2 warps along N (64 cols each)
    const int mbw  = wm * 32;
    const int nbw  = wn * 64;

    // prologue load k-tile 0
    float4 rA = *(const float4*)&x[(size_t)toks[lrow] * D_MODEL + lkq * 4];
    float4 rB = *(const float4*)&W[(size_t)(n0 + lrow) * D_MODEL + lkq * 4];

    {
        float va[4] = {rA.x, rA.y, rA.z, rA.w};
        float vb[4] = {rB.x, rB.y, rB.z, rB.w};
#pragma unroll
        for (int j = 0; j < 4; j++) {
            int k = lkq * 4 + j;
            uint32_t h = f2tf32(va[j]);
            float hf = __uint_as_float(h);
            AsH[0][k][lrow] = hf;
            AsL[0][k][lrow] = __uint_as_float(f2tf32(va[j] - hf));
            uint32_t hb = f2tf32(vb[j]);
            float hbf = __uint_as_float(hb);
            BsH[0][k][lrow] = hbf;
            BsL[0][k][lrow] = __uint_as_float(f2tf32(vb[j] - hbf));
        }
    }
    __syncthreads();

    float acc[2][8][4];
#pragma unroll
    for (int mf = 0; mf < 2; mf++)
#pragma unroll
        for (int nf = 0; nf < 8; nf++)
#pragma unroll
            for (int q = 0; q < 4; q++) acc[mf][nf][q] = 0.f;

    const int nk = D_MODEL / TK;        // 128 k-tiles
    for (int kt = 0; kt < nk; kt++) {
        const int buf = kt & 1;
        if (kt + 1 < nk) {
            int k0 = (kt + 1) * TK;
            rA = *(const float4*)&x[(size_t)toks[lrow] * D_MODEL + k0 + lkq * 4];
            rB = *(const float4*)&W[(size_t)(n0 + lrow) * D_MODEL + k0 + lkq * 4];
        }

        // ---- A fragments (2 m-frags of 16 rows) ----
        uint32_t aH[2][4], aL[2][4];
#pragma unroll
        for (int mf = 0; mf < 2; mf++) {
            int rb = mbw + mf * 16 + grp;
            aH[mf][0] = __float_as_uint(AsH[buf][tc    ][rb    ]);
            aH[mf][1] = __float_as_uint(AsH[buf][tc    ][rb + 8]);
            aH[mf][2] = __float_as_uint(AsH[buf][tc + 4][rb    ]);
            aH[mf][3] = __float_as_uint(AsH[buf][tc + 4][rb + 8]);
            aL[mf][0] = __float_as_uint(AsL[buf][tc    ][rb    ]);
            aL[mf][1] = __float_as_uint(AsL[buf][tc    ][rb + 8]);
            aL[mf][2] = __float_as_uint(AsL[buf][tc + 4][rb    ]);
            aL[mf][3] = __float_as_uint(AsL[buf][tc + 4][rb + 8]);
        }

        // ---- B fragments (8 n-frags of 8 cols), 3xTF32 accumulate ----
#pragma unroll
        for (int nf = 0; nf < 8; nf++) {
            int cb = nbw + nf * 8 + grp;
            uint32_t bH0 = __float_as_uint(BsH[buf][tc    ][cb]);
            uint32_t bH1 = __float_as_uint(BsH[buf][tc + 4][cb]);
            uint32_t bL0 = __float_as_uint(BsL[buf][tc    ][cb]);
            uint32_t bL1 = __float_as_uint(BsL[buf][tc + 4][cb]);
#pragma unroll
            for (int mf = 0; mf < 2; mf++) {
                mma_tf32(acc[mf][nf][0], acc[mf][nf][1], acc[mf][nf][2], acc[mf][nf][3],
                         aL[mf][0], aL[mf][1], aL[mf][2], aL[mf][3], bH0, bH1);
                mma_tf32(acc[mf][nf][0], acc[mf][nf][1], acc[mf][nf][2], acc[mf][nf][3],
                         aH[mf][0], aH[mf][1], aH[mf][2], aH[mf][3], bL0, bL1);
                mma_tf32(acc[mf][nf][0], acc[mf][nf][1], acc[mf][nf][2], acc[mf][nf][3],
                         aH[mf][0], aH[mf][1], aH[mf][2], aH[mf][3], bH0, bH1);
            }
        }

        if (kt + 1 < nk) {
            const int nb = buf ^ 1;
            float va[4] = {rA.x, rA.y, rA.z, rA.w};
            float vb[4] = {rB.x, rB.y, rB.z, rB.w};
#pragma unroll
            for (int j = 0; j < 4; j++) {
                int k = lkq * 4 + j;
                uint32_t h = f2tf32(va[j]);
                float hf = __uint_as_float(h);
                AsH[nb][k][lrow] = hf;
                AsL[nb][k][lrow] = __uint_as_float(f2tf32(va[j] - hf));
                uint32_t hb = f2tf32(vb[j]);
                float hbf = __uint_as_float(hb);
                BsH[nb][k][lrow] = hbf;
                BsL[nb][k][lrow] = __uint_as_float(f2tf32(vb[j] - hbf));
            }
            __syncthreads();
        }
    }

    // ---- epilogue: D fragment (grp,2tc) / (grp+8,2tc) rows/cols ----
#pragma unroll
    for (int mf = 0; mf < 2; mf++) {
        int m1 = m0 + mbw + mf * 16 + grp;
        int m2 = m1 + 8;
#pragma unroll
        for (int nf = 0; nf < 8; nf++) {
            int nc = n0 + nbw + nf * 8 + tc * 2;
            if (m1 < cnt) {
                float2 v = make_float2(acc[mf][nf][0], acc[mf][nf][1]);
                *(float2*)&d_ybuf[(size_t)(e * CAPACITY + m1) * D_MODEL + nc] = v;
            }
            if (m2 < cnt) {
                float2 v = make_float2(acc[mf][nf][2], acc[mf][nf][3]);
                *(float2*)&d_ybuf[(size_t)(e * CAPACITY + m2) * D_MODEL + nc] = v;
            }
        }
    }
}

// ---------------- kernel 3: combine (gather + weighted sum) ------------------
__global__ __launch_bounds__(256) void combine_kernel(float* __restrict__ out) {
    const int n = blockIdx.x;
    const int d = threadIdx.x * 4;

    const int   s0 = d_slot[n * 2 + 0];
    const int   s1 = d_slot[n * 2 + 1];
    const float w0 = d_wgt[n * 2 + 0];
    const float w1 = d_wgt[n * 2 + 1];

    float4 acc = make_float4(0.f, 0.f, 0.f, 0.f);
    if (s0 >= 0) {
        float4 v = *(const float4*)&d_ybuf[(size_t)s0 * D_MODEL + d];
        acc.x += w0 * v.x; acc.y += w0 * v.y; acc.z += w0 * v.z; acc.w += w0 * v.w;
    }
    if (s1 >= 0) {
        float4 v = *(const float4*)&d_ybuf[(size_t)s1 * D_MODEL + d];
        acc.x += w1 * v.x; acc.y += w1 * v.y; acc.z += w1 * v.z; acc.w += w1 * v.w;
    }
    *(float4*)&out[(size_t)n * D_MODEL + d] = acc;
}

// ---------------- launch ------------------------------------------------------
extern "C" void kernel_launch(void* const* d_in, const int* in_sizes, int n_in,
                              void* d_out, int out_size) {
    const float* x  = (const float*)d_in[0];   // [4096, 1024]
    const float* gw = (const float*)d_in[1];   // [64, 1024]
    const float* ew = (const float*)d_in[2];   // [64, 1024, 1024]
    float* out = (float*)d_out;                // [4096, 1024]

    zero_counts_kernel<<<1, 64>>>();
    route_kernel<<<N_TOKENS / 64, 256>>>(x, gw);
    {
        dim3 grid(D_MODEL / TN, CAPACITY / TM, NUM_EXPERTS);  // (8, 4, 64)
        expert_gemm_kernel<<<grid, 256>>>(x, ew);
    }
    combine_kernel<<<N_TOKENS, 256>>>(out);
}

// round 10
// speedup vs baseline: 1.5366x; 1.5366x over previous
#include <cuda_runtime.h>
#include <cuda_bf16.h>
#include <math.h>
#include <stdint.h>

#define NUM_EXPERTS 64
#define D_MODEL     1024
#define N_TOKENS    4096
#define CAPACITY    512

// ---------------- scratch (static device globals; no runtime allocation) ----
__device__ int   d_count[NUM_EXPERTS];
__device__ int   d_tok[NUM_EXPERTS * CAPACITY];
__device__ int   d_slot[N_TOKENS * 2];
__device__ float d_wgt[N_TOKENS * 2];
__device__ float d_ybuf[(size_t)NUM_EXPERTS * CAPACITY * D_MODEL];   // 128 MiB

// ---------------- kernel 0 ---------------------------------------------------
__global__ void zero_counts_kernel() {
    if (threadIdx.x < NUM_EXPERTS) d_count[threadIdx.x] = 0;
}

// ---------------- kernel 1: gating GEMM + top-2 + routing (verified) ---------
__global__ __launch_bounds__(256) void route_kernel(const float* __restrict__ x,
                                                    const float* __restrict__ gw) {
    __shared__ float Xs[32][64];
    __shared__ float Gs[32][64];
    __shared__ float Ls[64][65];

    const int t0  = blockIdx.x * 64;
    const int tid = threadIdx.x;
    const int tx  = tid & 15;
    const int ty  = tid >> 4;

    float acc[4][4];
#pragma unroll
    for (int i = 0; i < 4; i++)
#pragma unroll
        for (int j = 0; j < 4; j++) acc[i][j] = 0.f;

    for (int k0 = 0; k0 < D_MODEL; k0 += 32) {
#pragma unroll
        for (int i = 0; i < 2; i++) {
            int idx = tid + i * 256;
            int row = idx >> 3;
            int kq  = idx & 7;
            float4 v = *(const float4*)&x[(size_t)(t0 + row) * D_MODEL + k0 + kq * 4];
            Xs[kq * 4 + 0][row] = v.x;
            Xs[kq * 4 + 1][row] = v.y;
            Xs[kq * 4 + 2][row] = v.z;
            Xs[kq * 4 + 3][row] = v.w;
            float4 g = *(const float4*)&gw[(size_t)row * D_MODEL + k0 + kq * 4];
            Gs[kq * 4 + 0][row] = g.x;
            Gs[kq * 4 + 1][row] = g.y;
            Gs[kq * 4 + 2][row] = g.z;
            Gs[kq * 4 + 3][row] = g.w;
        }
        __syncthreads();
#pragma unroll
        for (int kk = 0; kk < 32; kk++) {
            float a[4], b[4];
            *(float4*)a = *(const float4*)&Xs[kk][ty * 4];
            *(float4*)b = *(const float4*)&Gs[kk][tx * 4];
#pragma unroll
            for (int i = 0; i < 4; i++)
#pragma unroll
                for (int j = 0; j < 4; j++) acc[i][j] += a[i] * b[j];
        }
        __syncthreads();
    }

#pragma unroll
    for (int i = 0; i < 4; i++)
#pragma unroll
        for (int j = 0; j < 4; j++) Ls[ty * 4 + i][tx * 4 + j] = acc[i][j];
    __syncthreads();

    if (tid < 64) {
        const int n = t0 + tid;
        float best = -INFINITY; int be = 0;
#pragma unroll
        for (int e = 0; e < NUM_EXPERTS; e++) {
            float v = Ls[tid][e];
            if (v > best) { best = v; be = e; }
        }
        float best2 = -INFINITY; int be2 = 0;
#pragma unroll
        for (int e = 0; e < NUM_EXPERTS; e++) {
            if (e == be) continue;
            float v = Ls[tid][e];
            if (v > best2) { best2 = v; be2 = e; }
        }
        float r  = expf(best2 - best);
        float w0 = 1.f / (1.f + r);
        float w1 = r / (1.f + r);

        int p0 = atomicAdd(&d_count[be],  1);
        int p1 = atomicAdd(&d_count[be2], 1);
        if (p0 < CAPACITY) {
            d_tok[be * CAPACITY + p0] = n;
            d_slot[n * 2 + 0] = be * CAPACITY + p0;
        } else d_slot[n * 2 + 0] = -1;
        if (p1 < CAPACITY) {
            d_tok[be2 * CAPACITY + p1] = n;
            d_slot[n * 2 + 1] = be2 * CAPACITY + p1;
        } else d_slot[n * 2 + 1] = -1;
        d_wgt[n * 2 + 0] = w0;
        d_wgt[n * 2 + 1] = w1;
    }
}

// ---------------- kernel 2: grouped GEMM, 3xBF16 (m16n8k16) ------------------
// y[m,n] = sum_k x[tok[m],k] * W_e[n,k]
// a = aH + aL (bf16 hi/lo). D += aH*bH + aH*bL + aL*bH  (drop aL*bL ~ 2^-16)
#define TM 128
#define TN 128
#define TK 16          // k per MMA / per smem tile
#define KP (TK / 2)    // packed bf16x2 words along k = 8
#define LDS_PAD 136    // (136*t + idx) mod 32 == (8t + idx) mod 32 -> conflict-free

__device__ __forceinline__ uint32_t pack_bf16(float lo, float hi) {
    __nv_bfloat162 h = __floats2bfloat162_rn(lo, hi);   // .x = lo (low 16 bits)
    return *reinterpret_cast<uint32_t*>(&h);
}

__device__ __forceinline__ void mma_bf16(float& d0, float& d1, float& d2, float& d3,
                                         uint32_t a0, uint32_t a1, uint32_t a2, uint32_t a3,
                                         uint32_t b0, uint32_t b1) {
    asm volatile(
        "mma.sync.aligned.m16n8k16.row.col.f32.bf16.bf16.f32 "
        "{%0,%1,%2,%3}, {%4,%5,%6,%7}, {%8,%9}, {%0,%1,%2,%3};"
        : "+f"(d0), "+f"(d1), "+f"(d2), "+f"(d3)
        : "r"(a0), "r"(a1), "r"(a2), "r"(a3), "r"(b0), "r"(b1));
}

__global__ __launch_bounds__(256, 2) void expert_gemm_kernel(const float* __restrict__ x,
                                                             const float* __restrict__ ew) {
    const int e = blockIdx.z;
    int cnt = d_count[e];
    if (cnt > CAPACITY) cnt = CAPACITY;
    const int m0 = blockIdx.y * TM;
    if (m0 >= cnt) return;
    const int n0 = blockIdx.x * TN;

    // packed bf16x2 hi/lo tiles, [kpair][row], double buffered (4 * 8.5KB = 34.8KB)
    __shared__ uint32_t AsH[2][KP][LDS_PAD];
    __shared__ uint32_t AsL[2][KP][LDS_PAD];
    __shared__ uint32_t BsH[2][KP][LDS_PAD];
    __shared__ uint32_t BsL[2][KP][LDS_PAD];
    __shared__ int      toks[TM];

    const int tid = threadIdx.x;
    if (tid < TM) {
        int gr = m0 + tid;
        toks[tid] = (gr < cnt) ? d_tok[e * CAPACITY + gr] : 0;
    }
    __syncthreads();

    const float* __restrict__ W = ew + (size_t)e * D_MODEL * D_MODEL;

    // loader: 512 float4 slots per matrix per k-tile16 (128 rows x 4 quads)
    // thread handles slots {tid, tid+256}
    int lrow[2], lq[2];
#pragma unroll
    for (int i = 0; i < 2; i++) {
        int s = tid + i * 256;
        lrow[i] = s >> 2;      // 0..127
        lq[i]   = s & 3;       // k quad: floats 4q..4q+3 -> kpairs 2q, 2q+1
    }

    // mma mapping
    const int lane = tid & 31;
    const int grp  = lane >> 2;         // 0..7
    const int tc   = lane & 3;          // 0..3
    const int wid  = tid >> 5;
    const int wm   = wid & 3;           // 4 warps along M
    const int wn   = wid >> 2;          // 2 warps along N
    const int mbw  = wm * 32;
    const int nbw  = wn * 64;

    float4 rA[2], rB[2];
    // prologue: global-load k-tile 0
#pragma unroll
    for (int i = 0; i < 2; i++) {
        rA[i] = *(const float4*)&x[(size_t)toks[lrow[i]] * D_MODEL + lq[i] * 4];
        rB[i] = *(const float4*)&W[(size_t)(n0 + lrow[i]) * D_MODEL + lq[i] * 4];
    }
#pragma unroll
    for (int i = 0; i < 2; i++) {
        float a0 = rA[i].x, a1 = rA[i].y, a2 = rA[i].z, a3 = rA[i].w;
        float b0 = rB[i].x, b1 = rB[i].y, b2 = rB[i].z, b3 = rB[i].w;
        float ah0 = __bfloat162float(__float2bfloat16_rn(a0));
        float ah1 = __bfloat162float(__float2bfloat16_rn(a1));
        float ah2 = __bfloat162float(__float2bfloat16_rn(a2));
        float ah3 = __bfloat162float(__float2bfloat16_rn(a3));
        float bh0 = __bfloat162float(__float2bfloat16_rn(b0));
        float bh1 = __bfloat162float(__float2bfloat16_rn(b1));
        float bh2 = __bfloat162float(__float2bfloat16_rn(b2));
        float bh3 = __bfloat162float(__float2bfloat16_rn(b3));
        int kp = lq[i] * 2, r = lrow[i];
        AsH[0][kp    ][r] = pack_bf16(ah0, ah1);
        AsH[0][kp + 1][r] = pack_bf16(ah2, ah3);
        AsL[0][kp    ][r] = pack_bf16(a0 - ah0, a1 - ah1);
        AsL[0][kp + 1][r] = pack_bf16(a2 - ah2, a3 - ah3);
        BsH[0][kp    ][r] = pack_bf16(bh0, bh1);
        BsH[0][kp + 1][r] = pack_bf16(bh2, bh3);
        BsL[0][kp    ][r] = pack_bf16(b0 - bh0, b1 - bh1);
        BsL[0][kp + 1][r] = pack_bf16(b2 - bh2, b3 - bh3);
    }
    __syncthreads();

    float acc[2][8][4];
#pragma unroll
    for (int mf = 0; mf < 2; mf++)
#pragma unroll
        for (int nf = 0; nf < 8; nf++)
#pragma unroll
            for (int q = 0; q < 4; q++) acc[mf][nf][q] = 0.f;

    const int nk = D_MODEL / TK;        // 64 k-tiles
    for (int kt = 0; kt < nk; kt++) {
        const int buf = kt & 1;
        if (kt + 1 < nk) {
            int k0 = (kt + 1) * TK;
#pragma unroll
            for (int i = 0; i < 2; i++) {
                rA[i] = *(const float4*)&x[(size_t)toks[lrow[i]] * D_MODEL + k0 + lq[i] * 4];
                rB[i] = *(const float4*)&W[(size_t)(n0 + lrow[i]) * D_MODEL + k0 + lq[i] * 4];
            }
        }

        // ---- A fragments: a0=(g, 2t..2t+1) a1=(g+8,..) a2=(g, 2t+8..) a3=(g+8,..)
        uint32_t aH[2][4], aL[2][4];
#pragma unroll
        for (int mf = 0; mf < 2; mf++) {
            int rb = mbw + mf * 16 + grp;
            aH[mf][0] = AsH[buf][tc    ][rb    ];
            aH[mf][1] = AsH[buf][tc    ][rb + 8];
            aH[mf][2] = AsH[buf][tc + 4][rb    ];
            aH[mf][3] = AsH[buf][tc + 4][rb + 8];
            aL[mf][0] = AsL[buf][tc    ][rb    ];
            aL[mf][1] = AsL[buf][tc    ][rb + 8];
            aL[mf][2] = AsL[buf][tc + 4][rb    ];
            aL[mf][3] = AsL[buf][tc + 4][rb + 8];
        }

        // ---- B fragments: b0=(k 2t..2t+1, col g) b1=(k 2t+8.., col g) ----
#pragma unroll
        for (int nf = 0; nf < 8; nf++) {
            int cb = nbw + nf * 8 + grp;
            uint32_t bH0 = BsH[buf][tc    ][cb];
            uint32_t bH1 = BsH[buf][tc + 4][cb];
            uint32_t bL0 = BsL[buf][tc    ][cb];
            uint32_t bL1 = BsL[buf][tc + 4][cb];
#pragma unroll
            for (int mf = 0; mf < 2; mf++) {
                mma_bf16(acc[mf][nf][0], acc[mf][nf][1], acc[mf][nf][2], acc[mf][nf][3],
                         aL[mf][0], aL[mf][1], aL[mf][2], aL[mf][3], bH0, bH1);
                mma_bf16(acc[mf][nf][0], acc[mf][nf][1], acc[mf][nf][2], acc[mf][nf][3],
                         aH[mf][0], aH[mf][1], aH[mf][2], aH[mf][3], bL0, bL1);
                mma_bf16(acc[mf][nf][0], acc[mf][nf][1], acc[mf][nf][2], acc[mf][nf][3],
                         aH[mf][0], aH[mf][1], aH[mf][2], aH[mf][3], bH0, bH1);
            }
        }

        if (kt + 1 < nk) {
            const int nb = buf ^ 1;
#pragma unroll
            for (int i = 0; i < 2; i++) {
                float a0 = rA[i].x, a1 = rA[i].y, a2 = rA[i].z, a3 = rA[i].w;
                float b0 = rB[i].x, b1 = rB[i].y, b2 = rB[i].z, b3 = rB[i].w;
                float ah0 = __bfloat162float(__float2bfloat16_rn(a0));
                float ah1 = __bfloat162float(__float2bfloat16_rn(a1));
                float ah2 = __bfloat162float(__float2bfloat16_rn(a2));
                float ah3 = __bfloat162float(__float2bfloat16_rn(a3));
                float bh0 = __bfloat162float(__float2bfloat16_rn(b0));
                float bh1 = __bfloat162float(__float2bfloat16_rn(b1));
                float bh2 = __bfloat162float(__float2bfloat16_rn(b2));
                float bh3 = __bfloat162float(__float2bfloat16_rn(b3));
                int kp = lq[i] * 2, r = lrow[i];
                AsH[nb][kp    ][r] = pack_bf16(ah0, ah1);
                AsH[nb][kp + 1][r] = pack_bf16(ah2, ah3);
                AsL[nb][kp    ][r] = pack_bf16(a0 - ah0, a1 - ah1);
                AsL[nb][kp + 1][r] = pack_bf16(a2 - ah2, a3 - ah3);
                BsH[nb][kp    ][r] = pack_bf16(bh0, bh1);
                BsH[nb][kp + 1][r] = pack_bf16(bh2, bh3);
                BsL[nb][kp    ][r] = pack_bf16(b0 - bh0, b1 - bh1);
                BsL[nb][kp + 1][r] = pack_bf16(b2 - bh2, b3 - bh3);
            }
            __syncthreads();
        }
    }

    // ---- epilogue: D frag rows (grp, grp+8), cols (2tc, 2tc+1) ----
#pragma unroll
    for (int mf = 0; mf < 2; mf++) {
        int m1 = m0 + mbw + mf * 16 + grp;
        int m2 = m1 + 8;
#pragma unroll
        for (int nf = 0; nf < 8; nf++) {
            int nc = n0 + nbw + nf * 8 + tc * 2;
            if (m1 < cnt) {
                float2 v = make_float2(acc[mf][nf][0], acc[mf][nf][1]);
                *(float2*)&d_ybuf[(size_t)(e * CAPACITY + m1) * D_MODEL + nc] = v;
            }
            if (m2 < cnt) {
                float2 v = make_float2(acc[mf][nf][2], acc[mf][nf][3]);
                *(float2*)&d_ybuf[(size_t)(e * CAPACITY + m2) * D_MODEL + nc] = v;
            }
        }
    }
}

// ---------------- kernel 3: combine (gather + weighted sum) ------------------
__global__ __launch_bounds__(256) void combine_kernel(float* __restrict__ out) {
    const int n = blockIdx.x;
    const int d = threadIdx.x * 4;

    const int   s0 = d_slot[n * 2 + 0];
    const int   s1 = d_slot[n * 2 + 1];
    const float w0 = d_wgt[n * 2 + 0];
    const float w1 = d_wgt[n * 2 + 1];

    float4 acc = make_float4(0.f, 0.f, 0.f, 0.f);
    if (s0 >= 0) {
        float4 v = *(const float4*)&d_ybuf[(size_t)s0 * D_MODEL + d];
        acc.x += w0 * v.x; acc.y += w0 * v.y; acc.z += w0 * v.z; acc.w += w0 * v.w;
    }
    if (s1 >= 0) {
        float4 v = *(const float4*)&d_ybuf[(size_t)s1 * D_MODEL + d];
        acc.x += w1 * v.x; acc.y += w1 * v.y; acc.z += w1 * v.z; acc.w += w1 * v.w;
    }
    *(float4*)&out[(size_t)n * D_MODEL + d] = acc;
}

// ---------------- launch ------------------------------------------------------
extern "C" void kernel_launch(void* const* d_in, const int* in_sizes, int n_in,
                              void* d_out, int out_size) {
    const float* x  = (const float*)d_in[0];   // [4096, 1024]
    const float* gw = (const float*)d_in[1];   // [64, 1024]
    const float* ew = (const float*)d_in[2];   // [64, 1024, 1024]
    float* out = (float*)d_out;                // [4096, 1024]

    zero_counts_kernel<<<1, 64>>>();
    route_kernel<<<N_TOKENS / 64, 256>>>(x, gw);
    {
        dim3 grid(D_MODEL / TN, CAPACITY / TM, NUM_EXPERTS);  // (8, 4, 64)
        expert_gemm_kernel<<<grid, 256>>>(x, ew);
    }
    combine_kernel<<<N_TOKENS, 256>>>(out);
}